// round 12
// baseline (speedup 1.0000x reference)
#include <cuda_runtime.h>
#include <cuda_fp16.h>
#include <math.h>
#include <stdint.h>

// Problem constants
#define NB   32
#define HGc  24
#define WGc  24
#define Dc   768
#define HIDc 384
#define G4c  1536
#define Tc   24
#define NSEQ 768
#define MTOT 18432

// Scratch (device globals). All MMA operands in fp16 fragment-native layouts.
static __device__ uint32_t g_z[(size_t)4 * MTOT * (G4c / 2)];   // z as half2
static __device__ uint32_t g_h[2][4][147456];                   // h fp16 A-frag (64-row tiles)
static __device__ float    g_c[4][NSEQ * HIDc];                 // cell state
static __device__ uint32_t g_x[(size_t)2 * 144 * 24 * 2048];    // x fp16 A-frag
static __device__ uint32_t g_wx[(size_t)4 * 12 * 24 * 2048];    // Wx fp16 B-frag
static __device__ uint32_t g_wh[(size_t)4 * 6 * 12 * 4096];     // Wh fp16 B-frag

// ---------------------------------------------------------------------------
// Helpers
// ---------------------------------------------------------------------------
__device__ __forceinline__ uint32_t smem_u32(const void* p) {
    uint32_t a;
    asm("{ .reg .u64 t; cvta.to.shared.u64 t, %1; cvt.u32.u64 %0, t; }" : "=r"(a) : "l"(p));
    return a;
}
__device__ __forceinline__ uint32_t pack_h2(float a, float b) {
    __half2 h = __floats2half2_rn(a, b);
    return *(uint32_t*)&h;
}
__device__ __forceinline__ float2 unpack_h2(uint32_t u) {
    return __half22float2(*(__half2*)&u);
}
__device__ __forceinline__ void cp16(uint32_t dst, const void* src) {
    asm volatile("cp.async.cg.shared.global [%0], [%1], 16;" :: "r"(dst), "l"(src));
}
#define CP_COMMIT() asm volatile("cp.async.commit_group;" ::: "memory")
#define CP_WAIT1()  asm volatile("cp.async.wait_group 1;" ::: "memory")
#define CP_WAIT0()  asm volatile("cp.async.wait_group 0;" ::: "memory")

__device__ __forceinline__ void mma_f16(float (&c)[4], const uint4& a,
                                        uint32_t b0, uint32_t b1) {
    asm volatile(
        "mma.sync.aligned.m16n8k16.row.col.f32.f16.f16.f32 "
        "{%0,%1,%2,%3}, {%4,%5,%6,%7}, {%8,%9}, {%0,%1,%2,%3};"
        : "+f"(c[0]), "+f"(c[1]), "+f"(c[2]), "+f"(c[3])
        : "r"(a.x), "r"(a.y), "r"(a.z), "r"(a.w), "r"(b0), "r"(b1));
}
__device__ __forceinline__ float sigf(float x)   { return 1.f / (1.f + __expf(-x)); }
__device__ __forceinline__ float tanhfa(float x) { return 2.f / (1.f + __expf(-2.f * x)) - 1.f; }

// ---------------------------------------------------------------------------
// Init: zero h (both parities) and c
// ---------------------------------------------------------------------------
__global__ void init_state_kernel() {
    size_t i = (size_t)blockIdx.x * blockDim.x + threadIdx.x;
    const size_t nh = (size_t)4 * 147456;
    const size_t nc = (size_t)4 * NSEQ * HIDc;
    if (i < nh) {
        ((uint32_t*)g_h)[i]      = 0u;
        ((uint32_t*)g_h)[nh + i] = 0u;
    }
    if (i < nc) ((float*)g_c)[i] = 0.f;
}

// ---------------------------------------------------------------------------
// Pre-pass: features -> fp16 A-fragment layout (m16n8k16).
// ---------------------------------------------------------------------------
__global__ void convert_x_frag(const float* __restrict__ feat) {
    size_t i = (size_t)blockIdx.x * blockDim.x + threadIdx.x;
    const size_t per_orient = (size_t)144 * 24 * 512;
    if (i >= 2 * per_orient) return;
    int orient = (int)(i / per_orient);
    size_t r = i - (size_t)orient * per_orient;
    int mtile = (int)(r / (24 * 512));
    int chunk = (int)((r >> 9) % 24);
    int u     = (int)(r & 511);
    int wm = u >> 7, k16 = (u >> 6) & 1, mt = (u >> 5) & 1, lane = u & 31;
    int row  = mtile * 128 + wm * 32 + mt * 16 + (lane >> 2);
    int colb = chunk * 32 + k16 * 16 + 2 * (lane & 3);

    uint32_t w[4];
#pragma unroll
    for (int rg = 0; rg < 4; rg++) {
        int m = row + 8 * (rg & 1);
        int k = colb + 8 * (rg >> 1);
        int rf;
        if (!orient) {
            rf = m;
        } else {
            int t  = m % 24;
            int nn = m / 24;
            int wg = nn % 24;
            int b  = nn / 24;
            rf = b * 576 + t * 24 + wg;
        }
        const float* p = feat + (size_t)rf * Dc + k;
        w[rg] = pack_h2(p[0], p[1]);
    }
    *(uint4*)(g_x + i * 4) = make_uint4(w[0], w[1], w[2], w[3]);
}

// ---------------------------------------------------------------------------
// Pre-pass: Wx -> fp16 B-fragment layout.
// ---------------------------------------------------------------------------
__global__ void convert_wx_frag(const float* __restrict__ w0, const float* __restrict__ w1,
                                const float* __restrict__ w2, const float* __restrict__ w3) {
    size_t i = (size_t)blockIdx.x * blockDim.x + threadIdx.x;
    const size_t per_dir = (size_t)12 * 24 * 512;
    if (i >= 4 * per_dir) return;
    int dir = (int)(i / per_dir);
    const float* W = (dir == 0) ? w0 : (dir == 1) ? w1 : (dir == 2) ? w2 : w3;
    size_t r = i - (size_t)dir * per_dir;
    int ntile = (int)(r / (24 * 512));
    int chunk = (int)((r >> 9) % 24);
    int u     = (int)(r & 511);
    int wn = u >> 8, k16 = (u >> 7) & 1, pp = (u >> 5) & 3, lane = u & 31;

    int k0 = chunk * 32 + k16 * 16 + 2 * (lane & 3);
    uint32_t w[4];
#pragma unroll
    for (int half = 0; half < 2; half++) {
        int n = ntile * 128 + wn * 64 + (pp * 2 + half) * 8 + (lane >> 2);
        w[half * 2 + 0] = pack_h2(W[(size_t)k0 * G4c + n],       W[(size_t)(k0 + 1) * G4c + n]);
        w[half * 2 + 1] = pack_h2(W[(size_t)(k0 + 8) * G4c + n], W[(size_t)(k0 + 9) * G4c + n]);
    }
    *(uint4*)(g_wx + i * 4) = make_uint4(w[0], w[1], w[2], w[3]);
}

// ---------------------------------------------------------------------------
// Pre-pass: Wh -> fp16 B-fragment layout.
// [dir][ctile(6)][chunk(12)][wn(4)][k16(2)][g(4)][lane(32)] uint4
// ---------------------------------------------------------------------------
__global__ void convert_wh_frag(const float* __restrict__ w0, const float* __restrict__ w1,
                                const float* __restrict__ w2, const float* __restrict__ w3) {
    size_t i = (size_t)blockIdx.x * blockDim.x + threadIdx.x;
    const size_t per_dir = (size_t)6 * 12 * 1024;
    if (i >= 4 * per_dir) return;
    int dir = (int)(i / per_dir);
    const float* W = (dir == 0) ? w0 : (dir == 1) ? w1 : (dir == 2) ? w2 : w3;
    size_t r = i - (size_t)dir * per_dir;
    int ctile = (int)(r / (12 * 1024));
    int chunk = (int)((r >> 10) % 12);
    int u     = (int)(r & 1023);
    int wn = u >> 8, k16 = (u >> 7) & 1, g = (u >> 5) & 3, lane = u & 31;

    int k0 = chunk * 32 + k16 * 16 + 2 * (lane & 3);
    uint32_t w[4];
#pragma unroll
    for (int half = 0; half < 2; half++) {
        int j = ctile * 64 + wn * 16 + half * 8 + (lane >> 2);
        int col = g * HIDc + j;
        w[half * 2 + 0] = pack_h2(W[(size_t)k0 * G4c + col],       W[(size_t)(k0 + 1) * G4c + col]);
        w[half * 2 + 1] = pack_h2(W[(size_t)(k0 + 8) * G4c + col], W[(size_t)(k0 + 9) * G4c + col]);
    }
    *(uint4*)(g_wh + i * 4) = make_uint4(w[0], w[1], w[2], w[3]);
}

// h fragment word offset (stores pair j, j+1). 64-row tiles (R9 layout).
__device__ __forceinline__ size_t h_word_off(int n, int j) {
    int ntile = n >> 6, rn = n & 63;
    int chunk = j >> 5, kk = j & 31;
    int k16 = kk >> 4, kr = kk & 15;
    int q   = (kr & 7) >> 1;
    int wm  = rn >> 5, r5 = rn & 31;
    int mt  = r5 >> 4, row16 = r5 & 15;
    int reg = ((kr >> 3) << 1) + (row16 >> 3);
    int lane = (row16 & 7) * 4 + q;
    return (size_t)(ntile * 12 + chunk) * 1024 +
           (size_t)((((wm * 2 + k16) * 2 + mt) * 32 + lane) * 4 + reg);
}

// ---------------------------------------------------------------------------
// Phase 1: z = x @ Wx + b. fp16 frag-native, 3-stage cp.async, 1 sync/chunk.
// CTA 128x128, K=768 in 24 chunks of 32. 8 warps = 4(M) x 2(N).
// SMEM: 3 stages x (2048 + 2048) words = 49152 B.
// ---------------------------------------------------------------------------
#define A1W 2048
#define B1W 2048
#define ST1W (A1W + B1W)

__global__ __launch_bounds__(256, 2)
void gemm_z_mma(const float* __restrict__ bhf, const float* __restrict__ bhb,
                const float* __restrict__ bvf, const float* __restrict__ bvb) {
    extern __shared__ uint32_t sm1[];
    const uint32_t sbase = smem_u32(sm1);

    const int tid  = threadIdx.x;
    const int lane = tid & 31;
    const int wid  = tid >> 5;
    const int wm   = wid & 3;
    const int wn   = wid >> 2;

    const int bx = blockIdx.x;
    const int by = blockIdx.y;
    const int orient = blockIdx.z;

    const int gc0  = bx * 128;
    const int half = (gc0 >= G4c) ? 1 : 0;
    const int wc0  = gc0 - half * G4c;
    const int dir  = orient * 2 + half;
    const int ntile = bx - half * 12;
    const float* bias = (orient == 0) ? (half ? bhb : bhf) : (half ? bvb : bvf);
    const int m0 = by * 128;

    const uint32_t* asrc = g_x + (size_t)(orient * 144 + by) * 24 * A1W + tid * 4;
    const uint32_t* bsrc = g_wx + ((size_t)dir * 12 + ntile) * 24 * B1W + tid * 4;

    float acc[2][8][4];
#pragma unroll
    for (int mt = 0; mt < 2; mt++)
#pragma unroll
        for (int nt = 0; nt < 8; nt++)
#pragma unroll
            for (int e = 0; e < 4; e++) acc[mt][nt][e] = 0.f;

#define LOAD1(c, st) do {                                                    \
    const uint32_t* as_ = asrc + (size_t)(c) * A1W;                          \
    const uint32_t* bs_ = bsrc + (size_t)(c) * B1W;                          \
    uint32_t ao = sbase + ((st) * ST1W + tid * 4) * 4;                       \
    uint32_t bo = ao + A1W * 4;                                              \
    _Pragma("unroll")                                                        \
    for (int q = 0; q < 2; q++) cp16(ao + q * 4096, as_ + q * 1024);         \
    _Pragma("unroll")                                                        \
    for (int q = 0; q < 2; q++) cp16(bo + q * 4096, bs_ + q * 1024);         \
    CP_COMMIT();                                                             \
} while (0)

    LOAD1(0, 0);
    LOAD1(1, 1);
    for (int c = 0; c < 24; c++) {
        const int st = c % 3;
        if (c < 23) CP_WAIT1();
        else        CP_WAIT0();
        __syncthreads();
        if (c + 2 < 24) LOAD1(c + 2, (c + 2) % 3);

        const uint4* A4 = (const uint4*)(sm1 + st * ST1W);
        const uint4* B4 = (const uint4*)(sm1 + st * ST1W + A1W);
#pragma unroll
        for (int k16 = 0; k16 < 2; k16++) {
            uint4 a0 = A4[((wm * 2 + k16) * 2 + 0) * 32 + lane];
            uint4 a1 = A4[((wm * 2 + k16) * 2 + 1) * 32 + lane];
#pragma unroll
            for (int pp = 0; pp < 4; pp++) {
                uint4 b = B4[((wn * 2 + k16) * 4 + pp) * 32 + lane];
                mma_f16(acc[0][2 * pp],     a0, b.x, b.y);
                mma_f16(acc[1][2 * pp],     a1, b.x, b.y);
                mma_f16(acc[0][2 * pp + 1], a0, b.z, b.w);
                mma_f16(acc[1][2 * pp + 1], a1, b.z, b.w);
            }
        }
    }
#undef LOAD1
    __syncthreads();

    uint32_t* Zt = g_z + (size_t)dir * MTOT * (G4c / 2);
#pragma unroll
    for (int mt = 0; mt < 2; mt++) {
        int r = m0 + wm * 32 + mt * 16 + (lane >> 2);
#pragma unroll
        for (int nt = 0; nt < 8; nt++) {
            int c = wc0 + wn * 64 + nt * 8 + 2 * (lane & 3);
            float bv0 = __ldg(&bias[c]);
            float bv1 = __ldg(&bias[c + 1]);
            Zt[(size_t)r * (G4c / 2) + (c >> 1)] =
                pack_h2(acc[mt][nt][0] + bv0, acc[mt][nt][1] + bv1);
            Zt[(size_t)(r + 8) * (G4c / 2) + (c >> 1)] =
                pack_h2(acc[mt][nt][2] + bv0, acc[mt][nt][3] + bv1);
        }
    }
}

// ---------------------------------------------------------------------------
// Phase 2: one LSTM step (R9 structure), 3-stage cp.async, 1 sync/chunk.
// CTA: 64 seqs x (4 gates x 64 cols), K=384 in 12 chunks of 32.
// 8 warps = 2(M) x 4(N). SMEM: 3 x (1024 + 4096) words = 61440 B.
// ---------------------------------------------------------------------------
#define A2W 1024
#define B2W 4096
#define ST2W (A2W + B2W)

__global__ __launch_bounds__(256, 2)
void lstm_step_mma(float* __restrict__ out, int s, int parity) {
    extern __shared__ uint32_t sm2[];
    const uint32_t sbase = smem_u32(sm2);

    const int dir = blockIdx.z;
    const bool forward = (dir == 0) || (dir == 2);
    const int t = forward ? s : (Tc - 1 - s);

    const int c0 = blockIdx.x * 64;
    const int n0 = blockIdx.y * 64;

    const uint32_t* hprev = g_h[parity][dir];
    uint32_t*       hnext = g_h[parity ^ 1][dir];
    float*          cst   = g_c[dir];
    const uint32_t* Z     = g_z + (size_t)dir * MTOT * (G4c / 2);

    const int tid  = threadIdx.x;
    const int lane = tid & 31;
    const int wid  = tid >> 5;
    const int wm   = wid & 1;
    const int wn   = wid >> 1;

    const uint32_t* hsrc = hprev + (size_t)blockIdx.y * 12 * A2W + tid * 4;
    const uint32_t* wsrc = g_wh + ((size_t)dir * 6 + blockIdx.x) * 12 * B2W + tid * 4;

    float acc[2][4][2][4];
#pragma unroll
    for (int mt = 0; mt < 2; mt++)
#pragma unroll
        for (int g = 0; g < 4; g++)
#pragma unroll
            for (int nt = 0; nt < 2; nt++)
#pragma unroll
                for (int e = 0; e < 4; e++) acc[mt][g][nt][e] = 0.f;

#define LOAD2(c, st) do {                                                    \
    const uint32_t* hs_ = hsrc + (size_t)(c) * A2W;                          \
    const uint32_t* ws_ = wsrc + (size_t)(c) * B2W;                          \
    uint32_t ho = sbase + ((st) * ST2W + tid * 4) * 4;                       \
    uint32_t wo = ho + A2W * 4;                                              \
    cp16(ho, hs_);                                                           \
    _Pragma("unroll")                                                        \
    for (int q = 0; q < 4; q++) cp16(wo + q * 4096, ws_ + q * 1024);         \
    CP_COMMIT();                                                             \
} while (0)

    LOAD2(0, 0);
    LOAD2(1, 1);
    for (int c = 0; c < 12; c++) {
        const int st = c % 3;
        if (c < 11) CP_WAIT1();
        else        CP_WAIT0();
        __syncthreads();
        if (c + 2 < 12) LOAD2(c + 2, (c + 2) % 3);

        const uint4* H4 = (const uint4*)(sm2 + st * ST2W);
        const uint4* W4 = (const uint4*)(sm2 + st * ST2W + A2W);
#pragma unroll
        for (int k16 = 0; k16 < 2; k16++) {
            uint4 a0 = H4[((wm * 2 + k16) * 2 + 0) * 32 + lane];
            uint4 a1 = H4[((wm * 2 + k16) * 2 + 1) * 32 + lane];
#pragma unroll
            for (int g = 0; g < 4; g++) {
                uint4 b = W4[((wn * 2 + k16) * 4 + g) * 32 + lane];
                mma_f16(acc[0][g][0], a0, b.x, b.y);
                mma_f16(acc[1][g][0], a1, b.x, b.y);
                mma_f16(acc[0][g][1], a0, b.z, b.w);
                mma_f16(acc[1][g][1], a1, b.z, b.w);
            }
        }
    }
#undef LOAD2

    // Epilogue: gates + state update + outputs
#pragma unroll
    for (int mt = 0; mt < 2; mt++) {
        int rbase = n0 + wm * 32 + mt * 16 + (lane >> 2);
#pragma unroll
        for (int nt = 0; nt < 2; nt++) {
            int j = c0 + wn * 16 + nt * 8 + 2 * (lane & 3);
#pragma unroll
            for (int hh = 0; hh < 2; hh++) {
                int n = rbase + 8 * hh;
                int e0 = 2 * hh;
                size_t zw = ((size_t)n * Tc + t) * (G4c / 2) + (j >> 1);
                float2 zi = unpack_h2(Z[zw]);
                float2 zf = unpack_h2(Z[zw + HIDc / 2]);
                float2 zg = unpack_h2(Z[zw + 2 * (HIDc / 2)]);
                float2 zo = unpack_h2(Z[zw + 3 * (HIDc / 2)]);

                float gi0 = acc[mt][0][nt][e0]     + zi.x;
                float gi1 = acc[mt][0][nt][e0 + 1] + zi.y;
                float gf0 = acc[mt][1][nt][e0]     + zf.x;
                float gf1 = acc[mt][1][nt][e0 + 1] + zf.y;
                float gg0 = acc[mt][2][nt][e0]     + zg.x;
                float gg1 = acc[mt][2][nt][e0 + 1] + zg.y;
                float go0 = acc[mt][3][nt][e0]     + zo.x;
                float go1 = acc[mt][3][nt][e0 + 1] + zo.y;

                size_t sidx = (size_t)n * HIDc + j;
                float2 cold = *(const float2*)&cst[sidx];
                float cn0 = sigf(gf0) * cold.x + sigf(gi0) * tanhfa(gg0);
                float cn1 = sigf(gf1) * cold.y + sigf(gi1) * tanhfa(gg1);
                *(float2*)&cst[sidx] = make_float2(cn0, cn1);

                float hn0 = sigf(go0) * tanhfa(cn0);
                float hn1 = sigf(go1) * tanhfa(cn1);

                hnext[h_word_off(n, j)] = pack_h2(hn0, hn1);

                size_t orow;
                if (dir < 2) {
                    orow = (size_t)n * WGc + t;
                } else {
                    int b  = n / WGc;
                    int wg = n % WGc;
                    orow = (size_t)b * (HGc * WGc) + (size_t)t * WGc + wg;
                }
                *(float2*)&out[orow * 1536 + (size_t)dir * HIDc + j] = make_float2(hn0, hn1);
            }
        }
    }
}

// ---------------------------------------------------------------------------
// Launch
// ---------------------------------------------------------------------------
extern "C" void kernel_launch(void* const* d_in, const int* in_sizes, int n_in,
                              void* d_out, int out_size) {
    const float* features = (const float*)d_in[0];
    const float* hf_Wx = (const float*)d_in[1];
    const float* hf_Wh = (const float*)d_in[2];
    const float* hf_b  = (const float*)d_in[3];
    const float* hb_Wx = (const float*)d_in[4];
    const float* hb_Wh = (const float*)d_in[5];
    const float* hb_b  = (const float*)d_in[6];
    const float* vf_Wx = (const float*)d_in[7];
    const float* vf_Wh = (const float*)d_in[8];
    const float* vf_b  = (const float*)d_in[9];
    const float* vb_Wx = (const float*)d_in[10];
    const float* vb_Wh = (const float*)d_in[11];
    const float* vb_b  = (const float*)d_in[12];
    float* out = (float*)d_out;

    const int smem1 = 3 * ST1W * 4;   // 49152
    const int smem2 = 3 * ST2W * 4;   // 61440
    cudaFuncSetAttribute(gemm_z_mma,    cudaFuncAttributeMaxDynamicSharedMemorySize, smem1);
    cudaFuncSetAttribute(lstm_step_mma, cudaFuncAttributeMaxDynamicSharedMemorySize, smem2);

    // init states
    {
        size_t n = (size_t)4 * NSEQ * HIDc;
        init_state_kernel<<<(int)((n + 255) / 256), 256>>>();
    }
    // pre-convert to fp16 fragment-native layouts
    {
        size_t nx = (size_t)2 * 144 * 24 * 512;
        convert_x_frag<<<(int)((nx + 255) / 256), 256>>>(features);
        size_t nwx = (size_t)4 * 12 * 24 * 512;
        convert_wx_frag<<<(int)((nwx + 255) / 256), 256>>>(hf_Wx, hb_Wx, vf_Wx, vb_Wx);
        size_t nwh = (size_t)4 * 6 * 12 * 1024;
        convert_wh_frag<<<(int)((nwh + 255) / 256), 256>>>(hf_Wh, hb_Wh, vf_Wh, vb_Wh);
    }
    // Phase 1
    {
        dim3 grid(3072 / 128, MTOT / 128, 2);
        gemm_z_mma<<<grid, 256, smem1>>>(hf_b, hb_b, vf_b, vb_b);
    }
    // Phase 2: 24 sequential step launches (proven best structure)
    {
        dim3 grid(HIDc / 64, NSEQ / 64, 4);
        for (int s = 0; s < Tc; s++) {
            lstm_step_mma<<<grid, 256, smem2>>>(out, s, s & 1);
        }
    }
}

// round 13
// speedup vs baseline: 1.0191x; 1.0191x over previous
#include <cuda_runtime.h>
#include <cuda_fp16.h>
#include <math.h>
#include <stdint.h>

// Problem constants
#define NB   32
#define HGc  24
#define WGc  24
#define Dc   768
#define HIDc 384
#define G4c  1536
#define Tc   24
#define NSEQ 768
#define MTOT 18432

// Scratch (device globals). All MMA operands in fp16 fragment-native layouts.
static __device__ uint32_t g_z[(size_t)4 * MTOT * (G4c / 2)];   // z as half2
static __device__ uint32_t g_h[2][4][147456];                   // h fp16 A-frag (64-row tiles)
static __device__ float    g_c[4][NSEQ * HIDc];                 // cell state
static __device__ uint32_t g_x[(size_t)2 * 144 * 24 * 2048];    // x fp16 A-frag
static __device__ uint32_t g_wx[(size_t)4 * 12 * 24 * 2048];    // Wx fp16 B-frag
static __device__ uint32_t g_wh[(size_t)4 * 6 * 12 * 4096];     // Wh fp16 B-frag

// ---------------------------------------------------------------------------
// Helpers
// ---------------------------------------------------------------------------
__device__ __forceinline__ uint32_t smem_u32(const void* p) {
    uint32_t a;
    asm("{ .reg .u64 t; cvta.to.shared.u64 t, %1; cvt.u32.u64 %0, t; }" : "=r"(a) : "l"(p));
    return a;
}
__device__ __forceinline__ uint32_t pack_h2(float a, float b) {
    __half2 h = __floats2half2_rn(a, b);
    return *(uint32_t*)&h;
}
__device__ __forceinline__ float2 unpack_h2(uint32_t u) {
    return __half22float2(*(__half2*)&u);
}
__device__ __forceinline__ void cp16(uint32_t dst, const void* src) {
    asm volatile("cp.async.cg.shared.global [%0], [%1], 16;" :: "r"(dst), "l"(src));
}
#define CP_COMMIT() asm volatile("cp.async.commit_group;" ::: "memory")
#define CP_WAIT1()  asm volatile("cp.async.wait_group 1;" ::: "memory")
#define CP_WAIT0()  asm volatile("cp.async.wait_group 0;" ::: "memory")

__device__ __forceinline__ void mma_f16(float (&c)[4], const uint4& a,
                                        uint32_t b0, uint32_t b1) {
    asm volatile(
        "mma.sync.aligned.m16n8k16.row.col.f32.f16.f16.f32 "
        "{%0,%1,%2,%3}, {%4,%5,%6,%7}, {%8,%9}, {%0,%1,%2,%3};"
        : "+f"(c[0]), "+f"(c[1]), "+f"(c[2]), "+f"(c[3])
        : "r"(a.x), "r"(a.y), "r"(a.z), "r"(a.w), "r"(b0), "r"(b1));
}
__device__ __forceinline__ float sigf(float x)   { return 1.f / (1.f + __expf(-x)); }
__device__ __forceinline__ float tanhfa(float x) { return 2.f / (1.f + __expf(-2.f * x)) - 1.f; }

// ---------------------------------------------------------------------------
// Init: zero h (both parities) and c
// ---------------------------------------------------------------------------
__global__ void init_state_kernel() {
    size_t i = (size_t)blockIdx.x * blockDim.x + threadIdx.x;
    const size_t nh = (size_t)4 * 147456;
    const size_t nc = (size_t)4 * NSEQ * HIDc;
    if (i < nh) {
        ((uint32_t*)g_h)[i]      = 0u;
        ((uint32_t*)g_h)[nh + i] = 0u;
    }
    if (i < nc) ((float*)g_c)[i] = 0.f;
}

// ---------------------------------------------------------------------------
// Pre-pass: features -> fp16 A-fragment layout (m16n8k16).
// ---------------------------------------------------------------------------
__global__ void convert_x_frag(const float* __restrict__ feat) {
    size_t i = (size_t)blockIdx.x * blockDim.x + threadIdx.x;
    const size_t per_orient = (size_t)144 * 24 * 512;
    if (i >= 2 * per_orient) return;
    int orient = (int)(i / per_orient);
    size_t r = i - (size_t)orient * per_orient;
    int mtile = (int)(r / (24 * 512));
    int chunk = (int)((r >> 9) % 24);
    int u     = (int)(r & 511);
    int wm = u >> 7, k16 = (u >> 6) & 1, mt = (u >> 5) & 1, lane = u & 31;
    int row  = mtile * 128 + wm * 32 + mt * 16 + (lane >> 2);
    int colb = chunk * 32 + k16 * 16 + 2 * (lane & 3);

    uint32_t w[4];
#pragma unroll
    for (int rg = 0; rg < 4; rg++) {
        int m = row + 8 * (rg & 1);
        int k = colb + 8 * (rg >> 1);
        int rf;
        if (!orient) {
            rf = m;
        } else {
            int t  = m % 24;
            int nn = m / 24;
            int wg = nn % 24;
            int b  = nn / 24;
            rf = b * 576 + t * 24 + wg;
        }
        const float* p = feat + (size_t)rf * Dc + k;
        w[rg] = pack_h2(p[0], p[1]);
    }
    *(uint4*)(g_x + i * 4) = make_uint4(w[0], w[1], w[2], w[3]);
}

// ---------------------------------------------------------------------------
// Pre-pass: Wx -> fp16 B-fragment layout.
// ---------------------------------------------------------------------------
__global__ void convert_wx_frag(const float* __restrict__ w0, const float* __restrict__ w1,
                                const float* __restrict__ w2, const float* __restrict__ w3) {
    size_t i = (size_t)blockIdx.x * blockDim.x + threadIdx.x;
    const size_t per_dir = (size_t)12 * 24 * 512;
    if (i >= 4 * per_dir) return;
    int dir = (int)(i / per_dir);
    const float* W = (dir == 0) ? w0 : (dir == 1) ? w1 : (dir == 2) ? w2 : w3;
    size_t r = i - (size_t)dir * per_dir;
    int ntile = (int)(r / (24 * 512));
    int chunk = (int)((r >> 9) % 24);
    int u     = (int)(r & 511);
    int wn = u >> 8, k16 = (u >> 7) & 1, pp = (u >> 5) & 3, lane = u & 31;

    int k0 = chunk * 32 + k16 * 16 + 2 * (lane & 3);
    uint32_t w[4];
#pragma unroll
    for (int half = 0; half < 2; half++) {
        int n = ntile * 128 + wn * 64 + (pp * 2 + half) * 8 + (lane >> 2);
        w[half * 2 + 0] = pack_h2(W[(size_t)k0 * G4c + n],       W[(size_t)(k0 + 1) * G4c + n]);
        w[half * 2 + 1] = pack_h2(W[(size_t)(k0 + 8) * G4c + n], W[(size_t)(k0 + 9) * G4c + n]);
    }
    *(uint4*)(g_wx + i * 4) = make_uint4(w[0], w[1], w[2], w[3]);
}

// ---------------------------------------------------------------------------
// Pre-pass: Wh -> fp16 B-fragment layout.
// [dir][ctile(6)][chunk(12)][wn(4)][k16(2)][g(4)][lane(32)] uint4
// ---------------------------------------------------------------------------
__global__ void convert_wh_frag(const float* __restrict__ w0, const float* __restrict__ w1,
                                const float* __restrict__ w2, const float* __restrict__ w3) {
    size_t i = (size_t)blockIdx.x * blockDim.x + threadIdx.x;
    const size_t per_dir = (size_t)6 * 12 * 1024;
    if (i >= 4 * per_dir) return;
    int dir = (int)(i / per_dir);
    const float* W = (dir == 0) ? w0 : (dir == 1) ? w1 : (dir == 2) ? w2 : w3;
    size_t r = i - (size_t)dir * per_dir;
    int ctile = (int)(r / (12 * 1024));
    int chunk = (int)((r >> 10) % 12);
    int u     = (int)(r & 1023);
    int wn = u >> 8, k16 = (u >> 7) & 1, g = (u >> 5) & 3, lane = u & 31;

    int k0 = chunk * 32 + k16 * 16 + 2 * (lane & 3);
    uint32_t w[4];
#pragma unroll
    for (int half = 0; half < 2; half++) {
        int j = ctile * 64 + wn * 16 + half * 8 + (lane >> 2);
        int col = g * HIDc + j;
        w[half * 2 + 0] = pack_h2(W[(size_t)k0 * G4c + col],       W[(size_t)(k0 + 1) * G4c + col]);
        w[half * 2 + 1] = pack_h2(W[(size_t)(k0 + 8) * G4c + col], W[(size_t)(k0 + 9) * G4c + col]);
    }
    *(uint4*)(g_wh + i * 4) = make_uint4(w[0], w[1], w[2], w[3]);
}

// h fragment word offset (stores pair j, j+1). 64-row tiles (R9 layout).
__device__ __forceinline__ size_t h_word_off(int n, int j) {
    int ntile = n >> 6, rn = n & 63;
    int chunk = j >> 5, kk = j & 31;
    int k16 = kk >> 4, kr = kk & 15;
    int q   = (kr & 7) >> 1;
    int wm  = rn >> 5, r5 = rn & 31;
    int mt  = r5 >> 4, row16 = r5 & 15;
    int reg = ((kr >> 3) << 1) + (row16 >> 3);
    int lane = (row16 & 7) * 4 + q;
    return (size_t)(ntile * 12 + chunk) * 1024 +
           (size_t)((((wm * 2 + k16) * 2 + mt) * 32 + lane) * 4 + reg);
}

// ---------------------------------------------------------------------------
// Phase 1: z = x @ Wx + b. fp16 frag-native, cp.async 2-stage (R9 ordering),
// K chunked by 64 (two contiguous 32-chunks per load) -> 12 iterations.
// SMEM: 2 stages x (4096 + 4096) words = 65536 B.
// ---------------------------------------------------------------------------
#define A1W 4096
#define B1W 4096

__global__ __launch_bounds__(256, 2)
void gemm_z_mma(const float* __restrict__ bhf, const float* __restrict__ bhb,
                const float* __restrict__ bvf, const float* __restrict__ bvb) {
    extern __shared__ uint32_t sm1[];
    const uint32_t sbase = smem_u32(sm1);

    const int tid  = threadIdx.x;
    const int lane = tid & 31;
    const int wid  = tid >> 5;
    const int wm   = wid & 3;
    const int wn   = wid >> 2;

    const int bx = blockIdx.x;
    const int by = blockIdx.y;
    const int orient = blockIdx.z;

    const int gc0  = bx * 128;
    const int half = (gc0 >= G4c) ? 1 : 0;
    const int wc0  = gc0 - half * G4c;
    const int dir  = orient * 2 + half;
    const int ntile = bx - half * 12;
    const float* bias = (orient == 0) ? (half ? bhb : bhf) : (half ? bvb : bvf);
    const int m0 = by * 128;

    const uint32_t* asrc = g_x + (size_t)(orient * 144 + by) * 24 * 2048 + tid * 4;
    const uint32_t* bsrc = g_wx + ((size_t)dir * 12 + ntile) * 24 * 2048 + tid * 4;

    float acc[2][8][4];
#pragma unroll
    for (int mt = 0; mt < 2; mt++)
#pragma unroll
        for (int nt = 0; nt < 8; nt++)
#pragma unroll
            for (int e = 0; e < 4; e++) acc[mt][nt][e] = 0.f;

#define LOAD1(c, buf) do {                                                   \
    const uint32_t* as_ = asrc + (size_t)(c) * A1W;                          \
    const uint32_t* bs_ = bsrc + (size_t)(c) * B1W;                          \
    uint32_t ao = sbase + ((buf) * A1W + tid * 4) * 4;                       \
    uint32_t bo = sbase + ((2 * A1W + (buf) * B1W) + tid * 4) * 4;           \
    _Pragma("unroll")                                                        \
    for (int q = 0; q < 4; q++) cp16(ao + q * 4096, as_ + q * 1024);         \
    _Pragma("unroll")                                                        \
    for (int q = 0; q < 4; q++) cp16(bo + q * 4096, bs_ + q * 1024);         \
    CP_COMMIT();                                                             \
} while (0)

    LOAD1(0, 0);
    for (int c = 0; c < 12; c++) {
        const int buf = c & 1;
        if (c + 1 < 12) { LOAD1(c + 1, buf ^ 1); CP_WAIT1(); }
        else            { CP_WAIT0(); }
        __syncthreads();

        const uint4* A4 = (const uint4*)(sm1 + buf * A1W);
        const uint4* B4 = (const uint4*)(sm1 + 2 * A1W + buf * B1W);
#pragma unroll
        for (int cc = 0; cc < 2; cc++) {
#pragma unroll
            for (int k16 = 0; k16 < 2; k16++) {
                uint4 a0 = A4[cc * 512 + ((wm * 2 + k16) * 2 + 0) * 32 + lane];
                uint4 a1 = A4[cc * 512 + ((wm * 2 + k16) * 2 + 1) * 32 + lane];
#pragma unroll
                for (int pp = 0; pp < 4; pp++) {
                    uint4 b = B4[cc * 512 + ((wn * 2 + k16) * 4 + pp) * 32 + lane];
                    mma_f16(acc[0][2 * pp],     a0, b.x, b.y);
                    mma_f16(acc[1][2 * pp],     a1, b.x, b.y);
                    mma_f16(acc[0][2 * pp + 1], a0, b.z, b.w);
                    mma_f16(acc[1][2 * pp + 1], a1, b.z, b.w);
                }
            }
        }
        __syncthreads();
    }
#undef LOAD1

    uint32_t* Zt = g_z + (size_t)dir * MTOT * (G4c / 2);
#pragma unroll
    for (int mt = 0; mt < 2; mt++) {
        int r = m0 + wm * 32 + mt * 16 + (lane >> 2);
#pragma unroll
        for (int nt = 0; nt < 8; nt++) {
            int c = wc0 + wn * 64 + nt * 8 + 2 * (lane & 3);
            float bv0 = __ldg(&bias[c]);
            float bv1 = __ldg(&bias[c + 1]);
            Zt[(size_t)r * (G4c / 2) + (c >> 1)] =
                pack_h2(acc[mt][nt][0] + bv0, acc[mt][nt][1] + bv1);
            Zt[(size_t)(r + 8) * (G4c / 2) + (c >> 1)] =
                pack_h2(acc[mt][nt][2] + bv0, acc[mt][nt][3] + bv1);
        }
    }
}

// ---------------------------------------------------------------------------
// Phase 2: one LSTM step (R9 structure), K chunked by 64 -> 6 iterations.
// SMEM: 2 stages x (2048 + 8192) words = 81920 B.
// ---------------------------------------------------------------------------
#define A2W 2048
#define B2W 8192

__global__ __launch_bounds__(256, 2)
void lstm_step_mma(float* __restrict__ out, int s, int parity) {
    extern __shared__ uint32_t sm2[];
    const uint32_t sbase = smem_u32(sm2);

    const int dir = blockIdx.z;
    const bool forward = (dir == 0) || (dir == 2);
    const int t = forward ? s : (Tc - 1 - s);

    const int c0 = blockIdx.x * 64;
    const int n0 = blockIdx.y * 64;

    const uint32_t* hprev = g_h[parity][dir];
    uint32_t*       hnext = g_h[parity ^ 1][dir];
    float*          cst   = g_c[dir];
    const uint32_t* Z     = g_z + (size_t)dir * MTOT * (G4c / 2);

    const int tid  = threadIdx.x;
    const int lane = tid & 31;
    const int wid  = tid >> 5;
    const int wm   = wid & 1;
    const int wn   = wid >> 1;

    const uint32_t* hsrc = hprev + (size_t)blockIdx.y * 12 * 1024 + tid * 4;
    const uint32_t* wsrc = g_wh + ((size_t)dir * 6 + blockIdx.x) * 12 * 4096 + tid * 4;

    float acc[2][4][2][4];
#pragma unroll
    for (int mt = 0; mt < 2; mt++)
#pragma unroll
        for (int g = 0; g < 4; g++)
#pragma unroll
            for (int nt = 0; nt < 2; nt++)
#pragma unroll
                for (int e = 0; e < 4; e++) acc[mt][g][nt][e] = 0.f;

#define LOAD2(c, buf) do {                                                   \
    const uint32_t* hs_ = hsrc + (size_t)(c) * A2W;                          \
    const uint32_t* ws_ = wsrc + (size_t)(c) * B2W;                          \
    uint32_t ho = sbase + ((buf) * A2W + tid * 4) * 4;                       \
    uint32_t wo = sbase + ((2 * A2W + (buf) * B2W) + tid * 4) * 4;           \
    _Pragma("unroll")                                                        \
    for (int q = 0; q < 2; q++) cp16(ho + q * 4096, hs_ + q * 1024);         \
    _Pragma("unroll")                                                        \
    for (int q = 0; q < 8; q++) cp16(wo + q * 4096, ws_ + q * 1024);         \
    CP_COMMIT();                                                             \
} while (0)

    LOAD2(0, 0);
    for (int c = 0; c < 6; c++) {
        const int buf = c & 1;
        if (c + 1 < 6) { LOAD2(c + 1, buf ^ 1); CP_WAIT1(); }
        else           { CP_WAIT0(); }
        __syncthreads();

        const uint4* H4 = (const uint4*)(sm2 + buf * A2W);
        const uint4* W4 = (const uint4*)(sm2 + 2 * A2W + buf * B2W);
#pragma unroll
        for (int cc = 0; cc < 2; cc++) {
#pragma unroll
            for (int k16 = 0; k16 < 2; k16++) {
                uint4 a0 = H4[cc * 256 + ((wm * 2 + k16) * 2 + 0) * 32 + lane];
                uint4 a1 = H4[cc * 256 + ((wm * 2 + k16) * 2 + 1) * 32 + lane];
#pragma unroll
                for (int g = 0; g < 4; g++) {
                    uint4 b = W4[cc * 1024 + ((wn * 2 + k16) * 4 + g) * 32 + lane];
                    mma_f16(acc[0][g][0], a0, b.x, b.y);
                    mma_f16(acc[1][g][0], a1, b.x, b.y);
                    mma_f16(acc[0][g][1], a0, b.z, b.w);
                    mma_f16(acc[1][g][1], a1, b.z, b.w);
                }
            }
        }
        __syncthreads();
    }
#undef LOAD2

    // Epilogue: gates + state update + outputs
#pragma unroll
    for (int mt = 0; mt < 2; mt++) {
        int rbase = n0 + wm * 32 + mt * 16 + (lane >> 2);
#pragma unroll
        for (int nt = 0; nt < 2; nt++) {
            int j = c0 + wn * 16 + nt * 8 + 2 * (lane & 3);
#pragma unroll
            for (int hh = 0; hh < 2; hh++) {
                int n = rbase + 8 * hh;
                int e0 = 2 * hh;
                size_t zw = ((size_t)n * Tc + t) * (G4c / 2) + (j >> 1);
                float2 zi = unpack_h2(Z[zw]);
                float2 zf = unpack_h2(Z[zw + HIDc / 2]);
                float2 zg = unpack_h2(Z[zw + 2 * (HIDc / 2)]);
                float2 zo = unpack_h2(Z[zw + 3 * (HIDc / 2)]);

                float gi0 = acc[mt][0][nt][e0]     + zi.x;
                float gi1 = acc[mt][0][nt][e0 + 1] + zi.y;
                float gf0 = acc[mt][1][nt][e0]     + zf.x;
                float gf1 = acc[mt][1][nt][e0 + 1] + zf.y;
                float gg0 = acc[mt][2][nt][e0]     + zg.x;
                float gg1 = acc[mt][2][nt][e0 + 1] + zg.y;
                float go0 = acc[mt][3][nt][e0]     + zo.x;
                float go1 = acc[mt][3][nt][e0 + 1] + zo.y;

                size_t sidx = (size_t)n * HIDc + j;
                float2 cold = *(const float2*)&cst[sidx];
                float cn0 = sigf(gf0) * cold.x + sigf(gi0) * tanhfa(gg0);
                float cn1 = sigf(gf1) * cold.y + sigf(gi1) * tanhfa(gg1);
                *(float2*)&cst[sidx] = make_float2(cn0, cn1);

                float hn0 = sigf(go0) * tanhfa(cn0);
                float hn1 = sigf(go1) * tanhfa(cn1);

                hnext[h_word_off(n, j)] = pack_h2(hn0, hn1);

                size_t orow;
                if (dir < 2) {
                    orow = (size_t)n * WGc + t;
                } else {
                    int b  = n / WGc;
                    int wg = n % WGc;
                    orow = (size_t)b * (HGc * WGc) + (size_t)t * WGc + wg;
                }
                *(float2*)&out[orow * 1536 + (size_t)dir * HIDc + j] = make_float2(hn0, hn1);
            }
        }
    }
}

// ---------------------------------------------------------------------------
// Launch
// ---------------------------------------------------------------------------
extern "C" void kernel_launch(void* const* d_in, const int* in_sizes, int n_in,
                              void* d_out, int out_size) {
    const float* features = (const float*)d_in[0];
    const float* hf_Wx = (const float*)d_in[1];
    const float* hf_Wh = (const float*)d_in[2];
    const float* hf_b  = (const float*)d_in[3];
    const float* hb_Wx = (const float*)d_in[4];
    const float* hb_Wh = (const float*)d_in[5];
    const float* hb_b  = (const float*)d_in[6];
    const float* vf_Wx = (const float*)d_in[7];
    const float* vf_Wh = (const float*)d_in[8];
    const float* vf_b  = (const float*)d_in[9];
    const float* vb_Wx = (const float*)d_in[10];
    const float* vb_Wh = (const float*)d_in[11];
    const float* vb_b  = (const float*)d_in[12];
    float* out = (float*)d_out;

    const int smem1 = 2 * (A1W + B1W) * 4;   // 65536
    const int smem2 = 2 * (A2W + B2W) * 4;   // 81920
    cudaFuncSetAttribute(gemm_z_mma,    cudaFuncAttributeMaxDynamicSharedMemorySize, smem1);
    cudaFuncSetAttribute(lstm_step_mma, cudaFuncAttributeMaxDynamicSharedMemorySize, smem2);

    // init states
    {
        size_t n = (size_t)4 * NSEQ * HIDc;
        init_state_kernel<<<(int)((n + 255) / 256), 256>>>();
    }
    // pre-convert to fp16 fragment-native layouts
    {
        size_t nx = (size_t)2 * 144 * 24 * 512;
        convert_x_frag<<<(int)((nx + 255) / 256), 256>>>(features);
        size_t nwx = (size_t)4 * 12 * 24 * 512;
        convert_wx_frag<<<(int)((nwx + 255) / 256), 256>>>(hf_Wx, hb_Wx, vf_Wx, vb_Wx);
        size_t nwh = (size_t)4 * 6 * 12 * 1024;
        convert_wh_frag<<<(int)((nwh + 255) / 256), 256>>>(hf_Wh, hb_Wh, vf_Wh, vb_Wh);
    }
    // Phase 1
    {
        dim3 grid(3072 / 128, MTOT / 128, 2);
        gemm_z_mma<<<grid, 256, smem1>>>(hf_b, hb_b, vf_b, vb_b);
    }
    // Phase 2: 24 sequential step launches (proven best structure)
    {
        dim3 grid(HIDc / 64, NSEQ / 64, 4);
        for (int s = 0; s < Tc; s++) {
            lstm_step_mma<<<grid, 256, smem2>>>(out, s, s & 1);
        }
    }
}

// round 14
// speedup vs baseline: 1.0557x; 1.0359x over previous
#include <cuda_runtime.h>
#include <cuda_fp16.h>
#include <math.h>
#include <stdint.h>

// Problem constants
#define NB   32
#define HGc  24
#define WGc  24
#define Dc   768
#define HIDc 384
#define G4c  1536
#define Tc   24
#define NSEQ 768
#define MTOT 18432

// Scratch (device globals). All MMA operands in fp16 fragment-native layouts.
static __device__ uint32_t g_z[(size_t)4 * MTOT * (G4c / 2)];   // z as half2
static __device__ uint32_t g_h[2][4][147456];                   // h fp16 A-frag (64-row tiles)
static __device__ float    g_c[4][NSEQ * HIDc];                 // cell state
static __device__ uint32_t g_x[(size_t)2 * 144 * 24 * 2048];    // x fp16 A-frag
static __device__ uint32_t g_wx[(size_t)4 * 12 * 24 * 2048];    // Wx fp16 B-frag
static __device__ uint32_t g_wh[(size_t)4 * 6 * 12 * 4096];     // Wh fp16 B-frag

// ---------------------------------------------------------------------------
// Helpers
// ---------------------------------------------------------------------------
__device__ __forceinline__ uint32_t smem_u32(const void* p) {
    uint32_t a;
    asm("{ .reg .u64 t; cvta.to.shared.u64 t, %1; cvt.u32.u64 %0, t; }" : "=r"(a) : "l"(p));
    return a;
}
__device__ __forceinline__ uint32_t pack_h2(float a, float b) {
    __half2 h = __floats2half2_rn(a, b);
    return *(uint32_t*)&h;
}
__device__ __forceinline__ float2 unpack_h2(uint32_t u) {
    return __half22float2(*(__half2*)&u);
}
__device__ __forceinline__ void cp16(uint32_t dst, const void* src) {
    asm volatile("cp.async.cg.shared.global [%0], [%1], 16;" :: "r"(dst), "l"(src));
}
#define CP_COMMIT() asm volatile("cp.async.commit_group;" ::: "memory")
#define CP_WAIT2()  asm volatile("cp.async.wait_group 2;" ::: "memory")
#define CP_WAIT1()  asm volatile("cp.async.wait_group 1;" ::: "memory")
#define CP_WAIT0()  asm volatile("cp.async.wait_group 0;" ::: "memory")

__device__ __forceinline__ void mma_f16(float (&c)[4], const uint4& a,
                                        uint32_t b0, uint32_t b1) {
    asm volatile(
        "mma.sync.aligned.m16n8k16.row.col.f32.f16.f16.f32 "
        "{%0,%1,%2,%3}, {%4,%5,%6,%7}, {%8,%9}, {%0,%1,%2,%3};"
        : "+f"(c[0]), "+f"(c[1]), "+f"(c[2]), "+f"(c[3])
        : "r"(a.x), "r"(a.y), "r"(a.z), "r"(a.w), "r"(b0), "r"(b1));
}
__device__ __forceinline__ float sigf(float x)   { return 1.f / (1.f + __expf(-x)); }
__device__ __forceinline__ float tanhfa(float x) { return 2.f / (1.f + __expf(-2.f * x)) - 1.f; }

// ---------------------------------------------------------------------------
// Init: zero h (both parities) and c
// ---------------------------------------------------------------------------
__global__ void init_state_kernel() {
    size_t i = (size_t)blockIdx.x * blockDim.x + threadIdx.x;
    const size_t nh = (size_t)4 * 147456;
    const size_t nc = (size_t)4 * NSEQ * HIDc;
    if (i < nh) {
        ((uint32_t*)g_h)[i]      = 0u;
        ((uint32_t*)g_h)[nh + i] = 0u;
    }
    if (i < nc) ((float*)g_c)[i] = 0.f;
}

// ---------------------------------------------------------------------------
// Merged pre-pass: features + Wx + Wh -> fp16 fragment layouts (one kernel).
// ---------------------------------------------------------------------------
#define NX4  ((size_t)2 * 144 * 24 * 512)
#define NWX4 ((size_t)4 * 12 * 24 * 512)
#define NWH4 ((size_t)4 * 6 * 12 * 1024)

__global__ void convert_all(const float* __restrict__ feat,
                            const float* __restrict__ x0, const float* __restrict__ x1,
                            const float* __restrict__ x2, const float* __restrict__ x3,
                            const float* __restrict__ h0, const float* __restrict__ h1,
                            const float* __restrict__ h2, const float* __restrict__ h3) {
    size_t i = (size_t)blockIdx.x * blockDim.x + threadIdx.x;
    if (i < NX4) {
        // features -> A-frag
        const size_t per_orient = NX4 / 2;
        int orient = (int)(i / per_orient);
        size_t r = i - (size_t)orient * per_orient;
        int mtile = (int)(r / (24 * 512));
        int chunk = (int)((r >> 9) % 24);
        int u     = (int)(r & 511);
        int wm = u >> 7, k16 = (u >> 6) & 1, mt = (u >> 5) & 1, lane = u & 31;
        int row  = mtile * 128 + wm * 32 + mt * 16 + (lane >> 2);
        int colb = chunk * 32 + k16 * 16 + 2 * (lane & 3);
        uint32_t w[4];
#pragma unroll
        for (int rg = 0; rg < 4; rg++) {
            int m = row + 8 * (rg & 1);
            int k = colb + 8 * (rg >> 1);
            int rf;
            if (!orient) {
                rf = m;
            } else {
                int t  = m % 24;
                int nn = m / 24;
                int wg = nn % 24;
                int b  = nn / 24;
                rf = b * 576 + t * 24 + wg;
            }
            const float* p = feat + (size_t)rf * Dc + k;
            w[rg] = pack_h2(p[0], p[1]);
        }
        *(uint4*)(g_x + i * 4) = make_uint4(w[0], w[1], w[2], w[3]);
    } else if (i < NX4 + NWX4) {
        // Wx -> B-frag
        size_t ii = i - NX4;
        const size_t per_dir = NWX4 / 4;
        int dir = (int)(ii / per_dir);
        const float* W = (dir == 0) ? x0 : (dir == 1) ? x1 : (dir == 2) ? x2 : x3;
        size_t r = ii - (size_t)dir * per_dir;
        int ntile = (int)(r / (24 * 512));
        int chunk = (int)((r >> 9) % 24);
        int u     = (int)(r & 511);
        int wn = u >> 8, k16 = (u >> 7) & 1, pp = (u >> 5) & 3, lane = u & 31;
        int k0 = chunk * 32 + k16 * 16 + 2 * (lane & 3);
        uint32_t w[4];
#pragma unroll
        for (int half = 0; half < 2; half++) {
            int n = ntile * 128 + wn * 64 + (pp * 2 + half) * 8 + (lane >> 2);
            w[half * 2 + 0] = pack_h2(W[(size_t)k0 * G4c + n],       W[(size_t)(k0 + 1) * G4c + n]);
            w[half * 2 + 1] = pack_h2(W[(size_t)(k0 + 8) * G4c + n], W[(size_t)(k0 + 9) * G4c + n]);
        }
        *(uint4*)(g_wx + ii * 4) = make_uint4(w[0], w[1], w[2], w[3]);
    } else if (i < NX4 + NWX4 + NWH4) {
        // Wh -> B-frag
        size_t ii = i - NX4 - NWX4;
        const size_t per_dir = NWH4 / 4;
        int dir = (int)(ii / per_dir);
        const float* W = (dir == 0) ? h0 : (dir == 1) ? h1 : (dir == 2) ? h2 : h3;
        size_t r = ii - (size_t)dir * per_dir;
        int ctile = (int)(r / (12 * 1024));
        int chunk = (int)((r >> 10) % 12);
        int u     = (int)(r & 1023);
        int wn = u >> 8, k16 = (u >> 7) & 1, g = (u >> 5) & 3, lane = u & 31;
        int k0 = chunk * 32 + k16 * 16 + 2 * (lane & 3);
        uint32_t w[4];
#pragma unroll
        for (int half = 0; half < 2; half++) {
            int j = ctile * 64 + wn * 16 + half * 8 + (lane >> 2);
            int col = g * HIDc + j;
            w[half * 2 + 0] = pack_h2(W[(size_t)k0 * G4c + col],       W[(size_t)(k0 + 1) * G4c + col]);
            w[half * 2 + 1] = pack_h2(W[(size_t)(k0 + 8) * G4c + col], W[(size_t)(k0 + 9) * G4c + col]);
        }
        *(uint4*)(g_wh + ii * 4) = make_uint4(w[0], w[1], w[2], w[3]);
    }
}

// h fragment word offset (stores pair j, j+1). 64-row tiles (R9 layout).
__device__ __forceinline__ size_t h_word_off(int n, int j) {
    int ntile = n >> 6, rn = n & 63;
    int chunk = j >> 5, kk = j & 31;
    int k16 = kk >> 4, kr = kk & 15;
    int q   = (kr & 7) >> 1;
    int wm  = rn >> 5, r5 = rn & 31;
    int mt  = r5 >> 4, row16 = r5 & 15;
    int reg = ((kr >> 3) << 1) + (row16 >> 3);
    int lane = (row16 & 7) * 4 + q;
    return (size_t)(ntile * 12 + chunk) * 1024 +
           (size_t)((((wm * 2 + k16) * 2 + mt) * 32 + lane) * 4 + reg);
}

// ---------------------------------------------------------------------------
// Phase 1: z = x @ Wx + b. fp16 frag-native, cp.async 2-stage (exact R9).
// ---------------------------------------------------------------------------
#define A1W 2048
#define B1W 2048

__global__ __launch_bounds__(256, 2)
void gemm_z_mma(const float* __restrict__ bhf, const float* __restrict__ bhb,
                const float* __restrict__ bvf, const float* __restrict__ bvb) {
    extern __shared__ uint32_t sm1[];
    const uint32_t sbase = smem_u32(sm1);

    const int tid  = threadIdx.x;
    const int lane = tid & 31;
    const int wid  = tid >> 5;
    const int wm   = wid & 3;
    const int wn   = wid >> 2;

    const int bx = blockIdx.x;
    const int by = blockIdx.y;
    const int orient = blockIdx.z;

    const int gc0  = bx * 128;
    const int half = (gc0 >= G4c) ? 1 : 0;
    const int wc0  = gc0 - half * G4c;
    const int dir  = orient * 2 + half;
    const int ntile = bx - half * 12;
    const float* bias = (orient == 0) ? (half ? bhb : bhf) : (half ? bvb : bvf);
    const int m0 = by * 128;

    const uint32_t* asrc = g_x + (size_t)(orient * 144 + by) * 24 * A1W + tid * 4;
    const uint32_t* bsrc = g_wx + ((size_t)dir * 12 + ntile) * 24 * B1W + tid * 4;

    float acc[2][8][4];
#pragma unroll
    for (int mt = 0; mt < 2; mt++)
#pragma unroll
        for (int nt = 0; nt < 8; nt++)
#pragma unroll
            for (int e = 0; e < 4; e++) acc[mt][nt][e] = 0.f;

#define LOAD1(c, buf) do {                                                   \
    const uint32_t* as_ = asrc + (size_t)(c) * A1W;                          \
    const uint32_t* bs_ = bsrc + (size_t)(c) * B1W;                          \
    uint32_t ao = sbase + ((buf) * A1W + tid * 4) * 4;                       \
    uint32_t bo = sbase + ((2 * A1W + (buf) * B1W) + tid * 4) * 4;           \
    _Pragma("unroll")                                                        \
    for (int q = 0; q < 2; q++) cp16(ao + q * 4096, as_ + q * 1024);         \
    _Pragma("unroll")                                                        \
    for (int q = 0; q < 2; q++) cp16(bo + q * 4096, bs_ + q * 1024);         \
    CP_COMMIT();                                                             \
} while (0)

    LOAD1(0, 0);
    for (int c = 0; c < 24; c++) {
        const int buf = c & 1;
        if (c + 1 < 24) { LOAD1(c + 1, buf ^ 1); CP_WAIT1(); }
        else            { CP_WAIT0(); }
        __syncthreads();

        const uint4* A4 = (const uint4*)(sm1 + buf * A1W);
        const uint4* B4 = (const uint4*)(sm1 + 2 * A1W + buf * B1W);
#pragma unroll
        for (int k16 = 0; k16 < 2; k16++) {
            uint4 a0 = A4[((wm * 2 + k16) * 2 + 0) * 32 + lane];
            uint4 a1 = A4[((wm * 2 + k16) * 2 + 1) * 32 + lane];
#pragma unroll
            for (int pp = 0; pp < 4; pp++) {
                uint4 b = B4[((wn * 2 + k16) * 4 + pp) * 32 + lane];
                mma_f16(acc[0][2 * pp],     a0, b.x, b.y);
                mma_f16(acc[1][2 * pp],     a1, b.x, b.y);
                mma_f16(acc[0][2 * pp + 1], a0, b.z, b.w);
                mma_f16(acc[1][2 * pp + 1], a1, b.z, b.w);
            }
        }
        __syncthreads();
    }
#undef LOAD1

    uint32_t* Zt = g_z + (size_t)dir * MTOT * (G4c / 2);
#pragma unroll
    for (int mt = 0; mt < 2; mt++) {
        int r = m0 + wm * 32 + mt * 16 + (lane >> 2);
#pragma unroll
        for (int nt = 0; nt < 8; nt++) {
            int c = wc0 + wn * 64 + nt * 8 + 2 * (lane & 3);
            float bv0 = __ldg(&bias[c]);
            float bv1 = __ldg(&bias[c + 1]);
            Zt[(size_t)r * (G4c / 2) + (c >> 1)] =
                pack_h2(acc[mt][nt][0] + bv0, acc[mt][nt][1] + bv1);
            Zt[(size_t)(r + 8) * (G4c / 2) + (c >> 1)] =
                pack_h2(acc[mt][nt][2] + bv0, acc[mt][nt][3] + bv1);
        }
    }
}

// ---------------------------------------------------------------------------
// Phase 2: one LSTM step (R9 structure) + Z smem prefetch + fast tanh.
// CTA: 64 seqs x (4 gates x 64 cols), K=384 in 12 chunks of 32.
// SMEM: 2x(1024+4096) + Z 64x132 = 10240 + 8448 words = 74752 B.
// ---------------------------------------------------------------------------
#define A2W 1024
#define B2W 4096
#define ZOFFW (2 * (A2W + B2W))      // 10240
#define ZROWW 132                    // padded words per row (conflict-free)
#define SM2W  (ZOFFW + 64 * ZROWW)   // 18688 words

__global__ __launch_bounds__(256, 2)
void lstm_step_mma(float* __restrict__ out, int s, int parity) {
    extern __shared__ uint32_t sm2[];
    const uint32_t sbase = smem_u32(sm2);

    const int dir = blockIdx.z;
    const bool forward = (dir == 0) || (dir == 2);
    const int t = forward ? s : (Tc - 1 - s);

    const int c0 = blockIdx.x * 64;
    const int n0 = blockIdx.y * 64;

    const uint32_t* hprev = g_h[parity][dir];
    uint32_t*       hnext = g_h[parity ^ 1][dir];
    float*          cst   = g_c[dir];
    const uint32_t* Z     = g_z + (size_t)dir * MTOT * (G4c / 2);

    const int tid  = threadIdx.x;
    const int lane = tid & 31;
    const int wid  = tid >> 5;
    const int wm   = wid & 1;
    const int wn   = wid >> 1;

    const uint32_t* hsrc = hprev + (size_t)blockIdx.y * 12 * A2W + tid * 4;
    const uint32_t* wsrc = g_wh + ((size_t)dir * 6 + blockIdx.x) * 12 * B2W + tid * 4;

    float acc[2][4][2][4];
#pragma unroll
    for (int mt = 0; mt < 2; mt++)
#pragma unroll
        for (int g = 0; g < 4; g++)
#pragma unroll
            for (int nt = 0; nt < 2; nt++)
#pragma unroll
                for (int e = 0; e < 4; e++) acc[mt][g][nt][e] = 0.f;

#define LOAD2(c, buf) do {                                                   \
    const uint32_t* hs_ = hsrc + (size_t)(c) * A2W;                          \
    const uint32_t* ws_ = wsrc + (size_t)(c) * B2W;                          \
    uint32_t ho = sbase + ((buf) * A2W + tid * 4) * 4;                       \
    uint32_t wo = sbase + ((2 * A2W + (buf) * B2W) + tid * 4) * 4;           \
    cp16(ho, hs_);                                                           \
    _Pragma("unroll")                                                        \
    for (int q = 0; q < 4; q++) cp16(wo + q * 4096, ws_ + q * 1024);         \
    CP_COMMIT();                                                             \
} while (0)

    // chunk0, then Z prefetch (own group), then chunk1
    LOAD2(0, 0);
    {
        int zrow = tid >> 2;          // 0..63
        int zg   = tid & 3;           // gate
        uint32_t zdst = sbase + (ZOFFW + zrow * ZROWW + zg * 32) * 4;
        const uint32_t* zsrc = Z + ((size_t)(n0 + zrow) * Tc + t) * (G4c / 2)
                                 + zg * (HIDc / 2) + (c0 >> 1);
#pragma unroll
        for (int w = 0; w < 8; w++) cp16(zdst + w * 16, zsrc + w * 4);
        CP_COMMIT();
    }
    LOAD2(1, 1);

    for (int c = 0; c < 12; c++) {
        const int buf = c & 1;
        if (c == 0)      { CP_WAIT2(); }
        else if (c < 11) { LOAD2(c + 1, (c + 1) & 1); CP_WAIT1(); }
        else             { CP_WAIT0(); }
        __syncthreads();

        const uint4* H4 = (const uint4*)(sm2 + buf * A2W);
        const uint4* W4 = (const uint4*)(sm2 + 2 * A2W + buf * B2W);
#pragma unroll
        for (int k16 = 0; k16 < 2; k16++) {
            uint4 a0 = H4[((wm * 2 + k16) * 2 + 0) * 32 + lane];
            uint4 a1 = H4[((wm * 2 + k16) * 2 + 1) * 32 + lane];
#pragma unroll
            for (int g = 0; g < 4; g++) {
                uint4 b = W4[((wn * 2 + k16) * 4 + g) * 32 + lane];
                mma_f16(acc[0][g][0], a0, b.x, b.y);
                mma_f16(acc[1][g][0], a1, b.x, b.y);
                mma_f16(acc[0][g][1], a0, b.z, b.w);
                mma_f16(acc[1][g][1], a1, b.z, b.w);
            }
        }
        __syncthreads();
    }
#undef LOAD2

    // Epilogue: gates from smem Z + state update + outputs (fast exact tanh)
    const uint32_t* sZ = sm2 + ZOFFW;
#pragma unroll
    for (int mt = 0; mt < 2; mt++) {
        int rloc = wm * 32 + mt * 16 + (lane >> 2);
#pragma unroll
        for (int nt = 0; nt < 2; nt++) {
            int j = c0 + wn * 16 + nt * 8 + 2 * (lane & 3);
            int widx = wn * 8 + nt * 4 + (lane & 3);
#pragma unroll
            for (int hh = 0; hh < 2; hh++) {
                int rr = rloc + 8 * hh;
                int n  = n0 + rr;
                int e0 = 2 * hh;
                const uint32_t* zr = sZ + rr * ZROWW + widx;
                float2 zi = unpack_h2(zr[0]);
                float2 zf = unpack_h2(zr[32]);
                float2 zg = unpack_h2(zr[64]);
                float2 zo = unpack_h2(zr[96]);

                float gi0 = acc[mt][0][nt][e0]     + zi.x;
                float gi1 = acc[mt][0][nt][e0 + 1] + zi.y;
                float gf0 = acc[mt][1][nt][e0]     + zf.x;
                float gf1 = acc[mt][1][nt][e0 + 1] + zf.y;
                float gg0 = acc[mt][2][nt][e0]     + zg.x;
                float gg1 = acc[mt][2][nt][e0 + 1] + zg.y;
                float go0 = acc[mt][3][nt][e0]     + zo.x;
                float go1 = acc[mt][3][nt][e0 + 1] + zo.y;

                size_t sidx = (size_t)n * HIDc + j;
                float2 cold = *(const float2*)&cst[sidx];
                float cn0 = sigf(gf0) * cold.x + sigf(gi0) * tanhfa(gg0);
                float cn1 = sigf(gf1) * cold.y + sigf(gi1) * tanhfa(gg1);
                *(float2*)&cst[sidx] = make_float2(cn0, cn1);

                float hn0 = sigf(go0) * tanhfa(cn0);
                float hn1 = sigf(go1) * tanhfa(cn1);

                hnext[h_word_off(n, j)] = pack_h2(hn0, hn1);

                size_t orow;
                if (dir < 2) {
                    orow = (size_t)n * WGc + t;
                } else {
                    int b  = n / WGc;
                    int wg = n % WGc;
                    orow = (size_t)b * (HGc * WGc) + (size_t)t * WGc + wg;
                }
                *(float2*)&out[orow * 1536 + (size_t)dir * HIDc + j] = make_float2(hn0, hn1);
            }
        }
    }
}

// ---------------------------------------------------------------------------
// Launch
// ---------------------------------------------------------------------------
extern "C" void kernel_launch(void* const* d_in, const int* in_sizes, int n_in,
                              void* d_out, int out_size) {
    const float* features = (const float*)d_in[0];
    const float* hf_Wx = (const float*)d_in[1];
    const float* hf_Wh = (const float*)d_in[2];
    const float* hf_b  = (const float*)d_in[3];
    const float* hb_Wx = (const float*)d_in[4];
    const float* hb_Wh = (const float*)d_in[5];
    const float* hb_b  = (const float*)d_in[6];
    const float* vf_Wx = (const float*)d_in[7];
    const float* vf_Wh = (const float*)d_in[8];
    const float* vf_b  = (const float*)d_in[9];
    const float* vb_Wx = (const float*)d_in[10];
    const float* vb_Wh = (const float*)d_in[11];
    const float* vb_b  = (const float*)d_in[12];
    float* out = (float*)d_out;

    const int smem1 = 2 * (A1W + B1W) * 4;   // 32768
    const int smem2 = SM2W * 4;              // 74752
    cudaFuncSetAttribute(gemm_z_mma,    cudaFuncAttributeMaxDynamicSharedMemorySize, smem1);
    cudaFuncSetAttribute(lstm_step_mma, cudaFuncAttributeMaxDynamicSharedMemorySize, smem2);

    // init states
    {
        size_t n = (size_t)4 * NSEQ * HIDc;
        init_state_kernel<<<(int)((n + 255) / 256), 256>>>();
    }
    // merged pre-pass conversion
    {
        size_t tot = NX4 + NWX4 + NWH4;
        convert_all<<<(int)((tot + 255) / 256), 256>>>(
            features, hf_Wx, hb_Wx, vf_Wx, vb_Wx, hf_Wh, hb_Wh, vf_Wh, vb_Wh);
    }
    // Phase 1
    {
        dim3 grid(3072 / 128, MTOT / 128, 2);
        gemm_z_mma<<<grid, 256, smem1>>>(hf_b, hb_b, vf_b, vb_b);
    }
    // Phase 2: 24 sequential step launches (proven best structure)
    {
        dim3 grid(HIDc / 64, NSEQ / 64, 4);
        for (int s = 0; s < Tc; s++) {
            lstm_step_mma<<<grid, 256, smem2>>>(out, s, s & 1);
        }
    }
}

// round 15
// speedup vs baseline: 1.0700x; 1.0136x over previous
#include <cuda_runtime.h>
#include <cuda_fp16.h>
#include <math.h>
#include <stdint.h>

// Problem constants
#define NB   32
#define HGc  24
#define WGc  24
#define Dc   768
#define HIDc 384
#define G4c  1536
#define Tc   24
#define NSEQ 768
#define MTOT 18432

// Scratch (device globals). All MMA operands in fp16 fragment-native layouts.
static __device__ uint32_t g_z[(size_t)4 * MTOT * (G4c / 2)];   // z as half2
static __device__ uint32_t g_h[2][4][147456];                   // h fp16 A-frag (64-row tiles)
static __device__ float    g_c[4][NSEQ * HIDc];                 // cell state
static __device__ uint32_t g_x[(size_t)2 * 144 * 24 * 2048];    // x fp16 A-frag
static __device__ uint32_t g_wx[(size_t)4 * 12 * 24 * 2048];    // Wx fp16 B-frag
static __device__ uint32_t g_wh[(size_t)4 * 6 * 12 * 4096];     // Wh fp16 B-frag

// ---------------------------------------------------------------------------
// Helpers
// ---------------------------------------------------------------------------
__device__ __forceinline__ uint32_t smem_u32(const void* p) {
    uint32_t a;
    asm("{ .reg .u64 t; cvta.to.shared.u64 t, %1; cvt.u32.u64 %0, t; }" : "=r"(a) : "l"(p));
    return a;
}
__device__ __forceinline__ uint32_t pack_h2(float a, float b) {
    __half2 h = __floats2half2_rn(a, b);
    return *(uint32_t*)&h;
}
__device__ __forceinline__ float2 unpack_h2(uint32_t u) {
    return __half22float2(*(__half2*)&u);
}
__device__ __forceinline__ void cp16(uint32_t dst, const void* src) {
    asm volatile("cp.async.cg.shared.global [%0], [%1], 16;" :: "r"(dst), "l"(src));
}
#define CP_COMMIT() asm volatile("cp.async.commit_group;" ::: "memory")
#define CP_WAIT1()  asm volatile("cp.async.wait_group 1;" ::: "memory")
#define CP_WAIT0()  asm volatile("cp.async.wait_group 0;" ::: "memory")

__device__ __forceinline__ void mma_f16(float (&c)[4], const uint4& a,
                                        uint32_t b0, uint32_t b1) {
    asm volatile(
        "mma.sync.aligned.m16n8k16.row.col.f32.f16.f16.f32 "
        "{%0,%1,%2,%3}, {%4,%5,%6,%7}, {%8,%9}, {%0,%1,%2,%3};"
        : "+f"(c[0]), "+f"(c[1]), "+f"(c[2]), "+f"(c[3])
        : "r"(a.x), "r"(a.y), "r"(a.z), "r"(a.w), "r"(b0), "r"(b1));
}
__device__ __forceinline__ float sigf(float x)   { return 1.f / (1.f + __expf(-x)); }
__device__ __forceinline__ float tanhfa(float x) { return 2.f / (1.f + __expf(-2.f * x)) - 1.f; }

// ---------------------------------------------------------------------------
// Init: zero h (both parities) and c
// ---------------------------------------------------------------------------
__global__ void init_state_kernel() {
    size_t i = (size_t)blockIdx.x * blockDim.x + threadIdx.x;
    const size_t nh = (size_t)4 * 147456;
    const size_t nc = (size_t)4 * NSEQ * HIDc;
    if (i < nh) {
        ((uint32_t*)g_h)[i]      = 0u;
        ((uint32_t*)g_h)[nh + i] = 0u;
    }
    if (i < nc) ((float*)g_c)[i] = 0.f;
}

// ---------------------------------------------------------------------------
// Merged pre-pass: features + Wx + Wh -> fp16 fragment layouts (one kernel).
// ---------------------------------------------------------------------------
#define NX4  ((size_t)2 * 144 * 24 * 512)
#define NWX4 ((size_t)4 * 12 * 24 * 512)
#define NWH4 ((size_t)4 * 6 * 12 * 1024)

__global__ void convert_all(const float* __restrict__ feat,
                            const float* __restrict__ x0, const float* __restrict__ x1,
                            const float* __restrict__ x2, const float* __restrict__ x3,
                            const float* __restrict__ h0, const float* __restrict__ h1,
                            const float* __restrict__ h2, const float* __restrict__ h3) {
    size_t i = (size_t)blockIdx.x * blockDim.x + threadIdx.x;
    if (i < NX4) {
        const size_t per_orient = NX4 / 2;
        int orient = (int)(i / per_orient);
        size_t r = i - (size_t)orient * per_orient;
        int mtile = (int)(r / (24 * 512));
        int chunk = (int)((r >> 9) % 24);
        int u     = (int)(r & 511);
        int wm = u >> 7, k16 = (u >> 6) & 1, mt = (u >> 5) & 1, lane = u & 31;
        int row  = mtile * 128 + wm * 32 + mt * 16 + (lane >> 2);
        int colb = chunk * 32 + k16 * 16 + 2 * (lane & 3);
        uint32_t w[4];
#pragma unroll
        for (int rg = 0; rg < 4; rg++) {
            int m = row + 8 * (rg & 1);
            int k = colb + 8 * (rg >> 1);
            int rf;
            if (!orient) {
                rf = m;
            } else {
                int t  = m % 24;
                int nn = m / 24;
                int wg = nn % 24;
                int b  = nn / 24;
                rf = b * 576 + t * 24 + wg;
            }
            const float* p = feat + (size_t)rf * Dc + k;
            w[rg] = pack_h2(p[0], p[1]);
        }
        *(uint4*)(g_x + i * 4) = make_uint4(w[0], w[1], w[2], w[3]);
    } else if (i < NX4 + NWX4) {
        size_t ii = i - NX4;
        const size_t per_dir = NWX4 / 4;
        int dir = (int)(ii / per_dir);
        const float* W = (dir == 0) ? x0 : (dir == 1) ? x1 : (dir == 2) ? x2 : x3;
        size_t r = ii - (size_t)dir * per_dir;
        int ntile = (int)(r / (24 * 512));
        int chunk = (int)((r >> 9) % 24);
        int u     = (int)(r & 511);
        int wn = u >> 8, k16 = (u >> 7) & 1, pp = (u >> 5) & 3, lane = u & 31;
        int k0 = chunk * 32 + k16 * 16 + 2 * (lane & 3);
        uint32_t w[4];
#pragma unroll
        for (int half = 0; half < 2; half++) {
            int n = ntile * 128 + wn * 64 + (pp * 2 + half) * 8 + (lane >> 2);
            w[half * 2 + 0] = pack_h2(W[(size_t)k0 * G4c + n],       W[(size_t)(k0 + 1) * G4c + n]);
            w[half * 2 + 1] = pack_h2(W[(size_t)(k0 + 8) * G4c + n], W[(size_t)(k0 + 9) * G4c + n]);
        }
        *(uint4*)(g_wx + ii * 4) = make_uint4(w[0], w[1], w[2], w[3]);
    } else if (i < NX4 + NWX4 + NWH4) {
        size_t ii = i - NX4 - NWX4;
        const size_t per_dir = NWH4 / 4;
        int dir = (int)(ii / per_dir);
        const float* W = (dir == 0) ? h0 : (dir == 1) ? h1 : (dir == 2) ? h2 : h3;
        size_t r = ii - (size_t)dir * per_dir;
        int ctile = (int)(r / (12 * 1024));
        int chunk = (int)((r >> 10) % 12);
        int u     = (int)(r & 1023);
        int wn = u >> 8, k16 = (u >> 7) & 1, g = (u >> 5) & 3, lane = u & 31;
        int k0 = chunk * 32 + k16 * 16 + 2 * (lane & 3);
        uint32_t w[4];
#pragma unroll
        for (int half = 0; half < 2; half++) {
            int j = ctile * 64 + wn * 16 + half * 8 + (lane >> 2);
            int col = g * HIDc + j;
            w[half * 2 + 0] = pack_h2(W[(size_t)k0 * G4c + col],       W[(size_t)(k0 + 1) * G4c + col]);
            w[half * 2 + 1] = pack_h2(W[(size_t)(k0 + 8) * G4c + col], W[(size_t)(k0 + 9) * G4c + col]);
        }
        *(uint4*)(g_wh + ii * 4) = make_uint4(w[0], w[1], w[2], w[3]);
    }
}

// h fragment word offset (stores pair j, j+1). 64-row tiles (R9 layout).
__device__ __forceinline__ size_t h_word_off(int n, int j) {
    int ntile = n >> 6, rn = n & 63;
    int chunk = j >> 5, kk = j & 31;
    int k16 = kk >> 4, kr = kk & 15;
    int q   = (kr & 7) >> 1;
    int wm  = rn >> 5, r5 = rn & 31;
    int mt  = r5 >> 4, row16 = r5 & 15;
    int reg = ((kr >> 3) << 1) + (row16 >> 3);
    int lane = (row16 & 7) * 4 + q;
    return (size_t)(ntile * 12 + chunk) * 1024 +
           (size_t)((((wm * 2 + k16) * 2 + mt) * 32 + lane) * 4 + reg);
}

// ---------------------------------------------------------------------------
// Phase 1: z = x @ Wx + b. fp16 frag-native, cp.async 2-stage (exact R9/R14).
// ---------------------------------------------------------------------------
#define A1W 2048
#define B1W 2048

__global__ __launch_bounds__(256, 2)
void gemm_z_mma(const float* __restrict__ bhf, const float* __restrict__ bhb,
                const float* __restrict__ bvf, const float* __restrict__ bvb) {
    extern __shared__ uint32_t sm1[];
    const uint32_t sbase = smem_u32(sm1);

    const int tid  = threadIdx.x;
    const int lane = tid & 31;
    const int wid  = tid >> 5;
    const int wm   = wid & 3;
    const int wn   = wid >> 2;

    const int bx = blockIdx.x;
    const int by = blockIdx.y;
    const int orient = blockIdx.z;

    const int gc0  = bx * 128;
    const int half = (gc0 >= G4c) ? 1 : 0;
    const int wc0  = gc0 - half * G4c;
    const int dir  = orient * 2 + half;
    const int ntile = bx - half * 12;
    const float* bias = (orient == 0) ? (half ? bhb : bhf) : (half ? bvb : bvf);
    const int m0 = by * 128;

    const uint32_t* asrc = g_x + (size_t)(orient * 144 + by) * 24 * A1W + tid * 4;
    const uint32_t* bsrc = g_wx + ((size_t)dir * 12 + ntile) * 24 * B1W + tid * 4;

    float acc[2][8][4];
#pragma unroll
    for (int mt = 0; mt < 2; mt++)
#pragma unroll
        for (int nt = 0; nt < 8; nt++)
#pragma unroll
            for (int e = 0; e < 4; e++) acc[mt][nt][e] = 0.f;

#define LOAD1(c, buf) do {                                                   \
    const uint32_t* as_ = asrc + (size_t)(c) * A1W;                          \
    const uint32_t* bs_ = bsrc + (size_t)(c) * B1W;                          \
    uint32_t ao = sbase + ((buf) * A1W + tid * 4) * 4;                       \
    uint32_t bo = sbase + ((2 * A1W + (buf) * B1W) + tid * 4) * 4;           \
    _Pragma("unroll")                                                        \
    for (int q = 0; q < 2; q++) cp16(ao + q * 4096, as_ + q * 1024);         \
    _Pragma("unroll")                                                        \
    for (int q = 0; q < 2; q++) cp16(bo + q * 4096, bs_ + q * 1024);         \
    CP_COMMIT();                                                             \
} while (0)

    LOAD1(0, 0);
    for (int c = 0; c < 24; c++) {
        const int buf = c & 1;
        if (c + 1 < 24) { LOAD1(c + 1, buf ^ 1); CP_WAIT1(); }
        else            { CP_WAIT0(); }
        __syncthreads();

        const uint4* A4 = (const uint4*)(sm1 + buf * A1W);
        const uint4* B4 = (const uint4*)(sm1 + 2 * A1W + buf * B1W);
#pragma unroll
        for (int k16 = 0; k16 < 2; k16++) {
            uint4 a0 = A4[((wm * 2 + k16) * 2 + 0) * 32 + lane];
            uint4 a1 = A4[((wm * 2 + k16) * 2 + 1) * 32 + lane];
#pragma unroll
            for (int pp = 0; pp < 4; pp++) {
                uint4 b = B4[((wn * 2 + k16) * 4 + pp) * 32 + lane];
                mma_f16(acc[0][2 * pp],     a0, b.x, b.y);
                mma_f16(acc[1][2 * pp],     a1, b.x, b.y);
                mma_f16(acc[0][2 * pp + 1], a0, b.z, b.w);
                mma_f16(acc[1][2 * pp + 1], a1, b.z, b.w);
            }
        }
        __syncthreads();
    }
#undef LOAD1

    uint32_t* Zt = g_z + (size_t)dir * MTOT * (G4c / 2);
#pragma unroll
    for (int mt = 0; mt < 2; mt++) {
        int r = m0 + wm * 32 + mt * 16 + (lane >> 2);
#pragma unroll
        for (int nt = 0; nt < 8; nt++) {
            int c = wc0 + wn * 64 + nt * 8 + 2 * (lane & 3);
            float bv0 = __ldg(&bias[c]);
            float bv1 = __ldg(&bias[c + 1]);
            Zt[(size_t)r * (G4c / 2) + (c >> 1)] =
                pack_h2(acc[mt][nt][0] + bv0, acc[mt][nt][1] + bv1);
            Zt[(size_t)(r + 8) * (G4c / 2) + (c >> 1)] =
                pack_h2(acc[mt][nt][2] + bv0, acc[mt][nt][3] + bv1);
        }
    }
}

// ---------------------------------------------------------------------------
// Phase 2: one LSTM step — SMEM-FREE mainloop. Fragments load directly
// LDG.128 -> registers (h and Wh are in exact fragment order), double-buffered
// at half-chunk (k16) granularity. Zero __syncthreads in the mainloop.
// SMEM holds only the Z prefetch (cp.async, waited once before epilogue).
// ---------------------------------------------------------------------------
#define ZROWW 132                    // padded words per Z row
#define SM2W  (64 * ZROWW)           // 8448 words = 33792 B

__global__ __launch_bounds__(256, 2)
void lstm_step_mma(float* __restrict__ out, int s, int parity) {
    extern __shared__ uint32_t sm2[];
    const uint32_t sbase = smem_u32(sm2);

    const int dir = blockIdx.z;
    const bool forward = (dir == 0) || (dir == 2);
    const int t = forward ? s : (Tc - 1 - s);

    const int c0 = blockIdx.x * 64;
    const int n0 = blockIdx.y * 64;

    const uint32_t* hprev = g_h[parity][dir];
    uint32_t*       hnext = g_h[parity ^ 1][dir];
    float*          cst   = g_c[dir];
    const uint32_t* Z     = g_z + (size_t)dir * MTOT * (G4c / 2);

    const int tid  = threadIdx.x;
    const int lane = tid & 31;
    const int wid  = tid >> 5;
    const int wm   = wid & 1;
    const int wn   = wid >> 1;

    // Z prefetch into smem (sole cp.async group)
    {
        int zrow = tid >> 2;
        int zg   = tid & 3;
        uint32_t zdst = sbase + (zrow * ZROWW + zg * 32) * 4;
        const uint32_t* zsrc = Z + ((size_t)(n0 + zrow) * Tc + t) * (G4c / 2)
                                 + zg * (HIDc / 2) + (c0 >> 1);
#pragma unroll
        for (int w = 0; w < 8; w++) cp16(zdst + w * 16, zsrc + w * 4);
        CP_COMMIT();
    }

    // Per-thread fragment base pointers (uint4 units)
    const uint4* Hb = (const uint4*)(hprev + (size_t)blockIdx.y * 12 * 1024);
    const uint4* Wb = (const uint4*)(g_wh + ((size_t)dir * 6 + blockIdx.x) * 12 * 4096);
    // within a chunk, for given k16: a(mt) index = ((wm*2+k16)*2+mt)*32+lane
    //                                b(g)  index = ((wn*2+k16)*4+g)*32+lane

    float acc[2][4][2][4];
#pragma unroll
    for (int mt = 0; mt < 2; mt++)
#pragma unroll
        for (int g = 0; g < 4; g++)
#pragma unroll
            for (int nt = 0; nt < 2; nt++)
#pragma unroll
                for (int e = 0; e < 4; e++) acc[mt][g][nt][e] = 0.f;

    uint4 a0, a1, b0, b1, b2, b3;
    // load half-chunk 0
    {
        const uint4* H = Hb;           // chunk 0
        const uint4* W = Wb;
        a0 = H[((wm * 2) * 2 + 0) * 32 + lane];
        a1 = H[((wm * 2) * 2 + 1) * 32 + lane];
        b0 = W[((wn * 2) * 4 + 0) * 32 + lane];
        b1 = W[((wn * 2) * 4 + 1) * 32 + lane];
        b2 = W[((wn * 2) * 4 + 2) * 32 + lane];
        b3 = W[((wn * 2) * 4 + 3) * 32 + lane];
    }

#pragma unroll
    for (int hc = 0; hc < 24; hc++) {
        uint4 na0, na1, nb0, nb1, nb2, nb3;
        if (hc + 1 < 24) {
            const int c   = (hc + 1) >> 1;
            const int k16 = (hc + 1) & 1;
            const uint4* H = Hb + c * 256;    // 1024 words = 256 uint4
            const uint4* W = Wb + c * 1024;   // 4096 words = 1024 uint4
            na0 = H[((wm * 2 + k16) * 2 + 0) * 32 + lane];
            na1 = H[((wm * 2 + k16) * 2 + 1) * 32 + lane];
            nb0 = W[((wn * 2 + k16) * 4 + 0) * 32 + lane];
            nb1 = W[((wn * 2 + k16) * 4 + 1) * 32 + lane];
            nb2 = W[((wn * 2 + k16) * 4 + 2) * 32 + lane];
            nb3 = W[((wn * 2 + k16) * 4 + 3) * 32 + lane];
        }
        // compute with current fragments
        mma_f16(acc[0][0][0], a0, b0.x, b0.y);
        mma_f16(acc[1][0][0], a1, b0.x, b0.y);
        mma_f16(acc[0][0][1], a0, b0.z, b0.w);
        mma_f16(acc[1][0][1], a1, b0.z, b0.w);
        mma_f16(acc[0][1][0], a0, b1.x, b1.y);
        mma_f16(acc[1][1][0], a1, b1.x, b1.y);
        mma_f16(acc[0][1][1], a0, b1.z, b1.w);
        mma_f16(acc[1][1][1], a1, b1.z, b1.w);
        mma_f16(acc[0][2][0], a0, b2.x, b2.y);
        mma_f16(acc[1][2][0], a1, b2.x, b2.y);
        mma_f16(acc[0][2][1], a0, b2.z, b2.w);
        mma_f16(acc[1][2][1], a1, b2.z, b2.w);
        mma_f16(acc[0][3][0], a0, b3.x, b3.y);
        mma_f16(acc[1][3][0], a1, b3.x, b3.y);
        mma_f16(acc[0][3][1], a0, b3.z, b3.w);
        mma_f16(acc[1][3][1], a1, b3.z, b3.w);

        if (hc + 1 < 24) {
            a0 = na0; a1 = na1;
            b0 = nb0; b1 = nb1; b2 = nb2; b3 = nb3;
        }
    }

    // Z visible to all threads
    CP_WAIT0();
    __syncthreads();

    // Epilogue: gates from smem Z + state update + outputs (fast exact tanh)
    const uint32_t* sZ = sm2;
#pragma unroll
    for (int mt = 0; mt < 2; mt++) {
        int rloc = wm * 32 + mt * 16 + (lane >> 2);
#pragma unroll
        for (int nt = 0; nt < 2; nt++) {
            int j = c0 + wn * 16 + nt * 8 + 2 * (lane & 3);
            int widx = wn * 8 + nt * 4 + (lane & 3);
#pragma unroll
            for (int hh = 0; hh < 2; hh++) {
                int rr = rloc + 8 * hh;
                int n  = n0 + rr;
                int e0 = 2 * hh;
                const uint32_t* zr = sZ + rr * ZROWW + widx;
                float2 zi = unpack_h2(zr[0]);
                float2 zf = unpack_h2(zr[32]);
                float2 zg = unpack_h2(zr[64]);
                float2 zo = unpack_h2(zr[96]);

                float gi0 = acc[mt][0][nt][e0]     + zi.x;
                float gi1 = acc[mt][0][nt][e0 + 1] + zi.y;
                float gf0 = acc[mt][1][nt][e0]     + zf.x;
                float gf1 = acc[mt][1][nt][e0 + 1] + zf.y;
                float gg0 = acc[mt][2][nt][e0]     + zg.x;
                float gg1 = acc[mt][2][nt][e0 + 1] + zg.y;
                float go0 = acc[mt][3][nt][e0]     + zo.x;
                float go1 = acc[mt][3][nt][e0 + 1] + zo.y;

                size_t sidx = (size_t)n * HIDc + j;
                float2 cold = *(const float2*)&cst[sidx];
                float cn0 = sigf(gf0) * cold.x + sigf(gi0) * tanhfa(gg0);
                float cn1 = sigf(gf1) * cold.y + sigf(gi1) * tanhfa(gg1);
                *(float2*)&cst[sidx] = make_float2(cn0, cn1);

                float hn0 = sigf(go0) * tanhfa(cn0);
                float hn1 = sigf(go1) * tanhfa(cn1);

                hnext[h_word_off(n, j)] = pack_h2(hn0, hn1);

                size_t orow;
                if (dir < 2) {
                    orow = (size_t)n * WGc + t;
                } else {
                    int b  = n / WGc;
                    int wg = n % WGc;
                    orow = (size_t)b * (HGc * WGc) + (size_t)t * WGc + wg;
                }
                *(float2*)&out[orow * 1536 + (size_t)dir * HIDc + j] = make_float2(hn0, hn1);
            }
        }
    }
}

// ---------------------------------------------------------------------------
// Launch
// ---------------------------------------------------------------------------
extern "C" void kernel_launch(void* const* d_in, const int* in_sizes, int n_in,
                              void* d_out, int out_size) {
    const float* features = (const float*)d_in[0];
    const float* hf_Wx = (const float*)d_in[1];
    const float* hf_Wh = (const float*)d_in[2];
    const float* hf_b  = (const float*)d_in[3];
    const float* hb_Wx = (const float*)d_in[4];
    const float* hb_Wh = (const float*)d_in[5];
    const float* hb_b  = (const float*)d_in[6];
    const float* vf_Wx = (const float*)d_in[7];
    const float* vf_Wh = (const float*)d_in[8];
    const float* vf_b  = (const float*)d_in[9];
    const float* vb_Wx = (const float*)d_in[10];
    const float* vb_Wh = (const float*)d_in[11];
    const float* vb_b  = (const float*)d_in[12];
    float* out = (float*)d_out;

    const int smem1 = 2 * (A1W + B1W) * 4;   // 32768
    const int smem2 = SM2W * 4;              // 33792
    cudaFuncSetAttribute(gemm_z_mma,    cudaFuncAttributeMaxDynamicSharedMemorySize, smem1);
    cudaFuncSetAttribute(lstm_step_mma, cudaFuncAttributeMaxDynamicSharedMemorySize, smem2);

    // init states
    {
        size_t n = (size_t)4 * NSEQ * HIDc;
        init_state_kernel<<<(int)((n + 255) / 256), 256>>>();
    }
    // merged pre-pass conversion
    {
        size_t tot = NX4 + NWX4 + NWH4;
        convert_all<<<(int)((tot + 255) / 256), 256>>>(
            features, hf_Wx, hb_Wx, vf_Wx, vb_Wx, hf_Wh, hb_Wh, vf_Wh, vb_Wh);
    }
    // Phase 1
    {
        dim3 grid(3072 / 128, MTOT / 128, 2);
        gemm_z_mma<<<grid, 256, smem1>>>(hf_b, hb_b, vf_b, vb_b);
    }
    // Phase 2: 24 sequential step launches
    {
        dim3 grid(HIDc / 64, NSEQ / 64, 4);
        for (int s = 0; s < Tc; s++) {
            lstm_step_mma<<<grid, 256, smem2>>>(out, s, s & 1);
        }
    }
}